// round 10
// baseline (speedup 1.0000x reference)
#include <cuda_runtime.h>
#include <cstdint>
#include <cstddef>

// ---------------- problem constants ----------------
static constexpr int NN   = 8192;
static constexpr int NSUP = 3;
static constexpr int DIN  = 32;
static constexpr int DOUT = 32;

// ---------------- tiling ----------------
static constexpr int KT   = 32;               // K per stage
static constexpr int MT   = 64;               // M rows per CTA
static constexpr int NSTG = 12;
static constexpr int STAGES_PER_S = NN / KT;            // 256
static constexpr int T_STAGES     = NSUP * STAGES_PER_S; // 768

static constexpr int ROW_STRIDE = 144;        // 128B data + 16B pad (conflict-free)
static constexpr int A_BYTES = MT * ROW_STRIDE;       // 9216
static constexpr int B_BYTES = DOUT * ROW_STRIDE;     // 4608
static constexpr int STAGE_BYTES = A_BYTES + B_BYTES; // 13824
static constexpr int B_OFF   = A_BYTES;
static constexpr int DYN_BYTES = NSTG * STAGE_BYTES;  // 165888

// scratch: preT[s][o][k] = rna_tf32(x@W[s] + b[s]) transposed
__device__ __align__(256) float g_preT[NSUP * DOUT * NN];

// ---------------- helpers ----------------
__device__ __forceinline__ uint32_t smem_u32(const void* p) {
    uint32_t a;
    asm("{ .reg .u64 t; cvta.to.shared.u64 t, %1; cvt.u32.u64 %0, t; }"
        : "=r"(a) : "l"(p));
    return a;
}
__device__ __forceinline__ void cp_async16(uint32_t dst, const void* src) {
    asm volatile("cp.async.cg.shared.global [%0], [%1], 16;"
                 :: "r"(dst), "l"(src) : "memory");
}
__device__ __forceinline__ void cp_commit() {
    asm volatile("cp.async.commit_group;" ::: "memory");
}
// wait until at most N async-groups of THIS thread are pending
template <int N>
__device__ __forceinline__ void cp_wait() {
    asm volatile("cp.async.wait_group %0;" :: "n"(N) : "memory");
}
__device__ __forceinline__ uint32_t f2tf32(float f) {
    uint32_t u;
    asm("cvt.rna.tf32.f32 %0, %1;" : "=r"(u) : "f"(f));
    return u;
}
__device__ __forceinline__ void mma_tf32(float* c, uint32_t a0, uint32_t a1,
                                         uint32_t a2, uint32_t a3,
                                         uint32_t b0, uint32_t b1) {
    asm volatile(
        "mma.sync.aligned.m16n8k8.row.col.f32.tf32.tf32.f32 "
        "{%0,%1,%2,%3}, {%4,%5,%6,%7}, {%8,%9}, {%0,%1,%2,%3};"
        : "+f"(c[0]), "+f"(c[1]), "+f"(c[2]), "+f"(c[3])
        : "r"(a0), "r"(a1), "r"(a2), "r"(a3), "r"(b0), "r"(b1));
}

// ---------------- precompute: preT[s][o][k] = rna_tf32(x@W + b) ----------------
__global__ void __launch_bounds__(256)
gcn_pre_kernel(const float* __restrict__ x, const float* __restrict__ W,
               const float* __restrict__ b) {
    int idx = blockIdx.x * 256 + threadIdx.x;   // [0, 786432)
    int o = idx & 31;
    int n = (idx >> 5) & (NN - 1);
    int s = idx >> 18;
    const float* xr = x + (size_t)n * DIN;
    const float* wc = W + (size_t)s * DIN * DOUT + o;
    float acc = b[s * DOUT + o];
#pragma unroll
    for (int i = 0; i < DIN; i++)
        acc = fmaf(xr[i], wc[i * DOUT], acc);
    g_preT[((size_t)s * DOUT + o) * NN + n] = __uint_as_float(f2tf32(acc));
}

// ---------------- main: classic multistage cp.async + mma.sync ----------------
__global__ void __launch_bounds__(128, 1)
gcn_main_kernel(const float* __restrict__ adj, float* __restrict__ out) {
    extern __shared__ __align__(256) char smem[];
    const uint32_t sb = smem_u32(smem);
    const int tid = threadIdx.x;
    const int m0  = blockIdx.x * MT;

    // ---- per-thread load addressing (A: 512 chunks, B: 256 chunks of 16B) ----
    uint32_t a_sm[4]; int a_go[4];
#pragma unroll
    for (int j = 0; j < 4; j++) {
        int id = j * 128 + tid;
        int r = id >> 3, c = id & 7;
        a_sm[j] = (uint32_t)(r * ROW_STRIDE + c * 16);
        a_go[j] = r * NN + c * 4;
    }
    uint32_t b_sm[2]; int b_go[2];
#pragma unroll
    for (int j = 0; j < 2; j++) {
        int id = j * 128 + tid;
        int o = id >> 3, c = id & 7;
        b_sm[j] = (uint32_t)(B_OFF + o * ROW_STRIDE + c * 16);
        b_go[j] = o * NN + c * 4;
    }

    // ---- per-thread MMA fragment mapping ----
    const int w  = tid >> 5;          // warp: rows 16w..16w+15
    const int L  = tid & 31;
    const int g  = L >> 2;            // groupID
    const int tg = L & 3;             // thread-in-group
    const int aoff0 = (w * 16 + g) * ROW_STRIDE;
    const int aoff1 = aoff0 + 8 * ROW_STRIDE;

    float acc[4][4];
#pragma unroll
    for (int i = 0; i < 4; i++)
#pragma unroll
        for (int j = 0; j < 4; j++) acc[i][j] = 0.0f;

    // ---- stage issue: 6 cp.async per thread ----
    auto issue_stage = [&](int t, int slot) {
        int s  = t >> 8;
        int k0 = (t & 255) << 5;
        uint32_t sbase = sb + slot * STAGE_BYTES;
        const float* aB = adj + (size_t)s * NN * NN + (size_t)m0 * NN + k0;
        const float* bB = g_preT + (size_t)s * DOUT * NN + k0;
#pragma unroll
        for (int j = 0; j < 4; j++) cp_async16(sbase + a_sm[j], aB + a_go[j]);
#pragma unroll
        for (int j = 0; j < 2; j++) cp_async16(sbase + b_sm[j], bB + b_go[j]);
    };

    // ---- prologue: stages 0..NSTG-2 ----
#pragma unroll
    for (int t = 0; t < NSTG - 1; t++) {
        issue_stage(t, t);
        cp_commit();
    }

    // ---- main loop ----
    int slot = 0;                      // slot of stage t
    int pslot = NSTG - 1;              // slot of stage t + NSTG-1
    for (int t = 0; t < T_STAGES; t++) {
        cp_wait<NSTG - 2>();           // this thread's group for stage t done
        __syncthreads();               // everyone's stage-t data visible;
                                       // all reads of stage t-1 finished
        if (t + NSTG - 1 < T_STAGES)
            issue_stage(t + NSTG - 1, pslot);
        cp_commit();                   // commit (possibly empty) keeps pending
                                       // count constant -> wait count correct in tail
        const char* sB = smem + slot * STAGE_BYTES;
#pragma unroll
        for (int j = 0; j < 4; j++) {  // kstep: k = 8j..8j+7
            const float* r0 = (const float*)(sB + aoff0);
            const float* r1 = (const float*)(sB + aoff1);
            uint32_t a0 = f2tf32(r0[j * 8 + tg]);
            uint32_t a1 = f2tf32(r1[j * 8 + tg]);
            uint32_t a2 = f2tf32(r0[j * 8 + tg + 4]);
            uint32_t a3 = f2tf32(r1[j * 8 + tg + 4]);
#pragma unroll
            for (int nf = 0; nf < 4; nf++) {
                const uint32_t* bp = (const uint32_t*)
                    (sB + B_OFF + (nf * 8 + g) * ROW_STRIDE) + j * 8 + tg;
                mma_tf32(acc[nf], a0, a1, a2, a3, bp[0], bp[4]);
            }
        }
        if (++slot == NSTG)  slot = 0;
        if (++pslot == NSTG) pslot = 0;
    }

    // ---- epilogue: relu + store ----
    const int mrow = m0 + w * 16 + g;
    float* o0 = out + (size_t)mrow * DOUT;
    float* o1 = out + (size_t)(mrow + 8) * DOUT;
#pragma unroll
    for (int nf = 0; nf < 4; nf++) {
        int col = nf * 8 + tg * 2;
        o0[col]     = fmaxf(acc[nf][0], 0.0f);
        o0[col + 1] = fmaxf(acc[nf][1], 0.0f);
        o1[col]     = fmaxf(acc[nf][2], 0.0f);
        o1[col + 1] = fmaxf(acc[nf][3], 0.0f);
    }
}

// ---------------- launch ----------------
extern "C" void kernel_launch(void* const* d_in, const int* in_sizes, int n_in,
                              void* d_out, int out_size) {
    const float* x   = (const float*)d_in[0];
    const float* adj = (const float*)d_in[1];
    const float* W   = (const float*)d_in[2];
    const float* b   = (const float*)d_in[3];
    float* out = (float*)d_out;

    cudaFuncSetAttribute(gcn_main_kernel,
                         cudaFuncAttributeMaxDynamicSharedMemorySize, DYN_BYTES);

    gcn_pre_kernel<<<(NSUP * NN * DOUT) / 256, 256>>>(x, W, b);
    gcn_main_kernel<<<NN / MT, 128, DYN_BYTES>>>(adj, out);
}